// round 13
// baseline (speedup 1.0000x reference)
#include <cuda_runtime.h>
#include <cuda_bf16.h>
#include <cuda_fp16.h>
#include <math.h>
#include <stdint.h>

#define LQ 4096
#define CDIM 1024
#define NHEADS 16
#define HDIM 64
#define C3 3072
// 0.125 * log2(e): fold softmax base-2 conversion into Q scaling
#define QSCALE 0.18033688011112042f

// ---------------------------------------------------------------------------
// Device-global scratch (all fp16)
// ---------------------------------------------------------------------------
__device__ __half g_x16[LQ * CDIM];                               // X single
__device__ __half g_a16[LQ * CDIM];                               // attn out single
__device__ __half g_wqh16[C3 * CDIM], g_wql16[C3 * CDIM];         // [N][K] hi/lo
__device__ __half g_woh16[CDIM * CDIM], g_wol16[CDIM * CDIM];     // [N][K] hi/lo
__device__ __half g_q16[NHEADS * LQ * HDIM];                      // Q*QSCALE single
__device__ __half g_k16[NHEADS * LQ * HDIM];                      // K single
__device__ __half g_v16[NHEADS * LQ * HDIM];                      // V single

// ---------------------------------------------------------------------------
// Warp-MMA helpers
// ---------------------------------------------------------------------------
__device__ __forceinline__ void mma16816h(float* c, const uint32_t* a,
                                          uint32_t b0, uint32_t b1) {
    asm volatile(
        "mma.sync.aligned.m16n8k16.row.col.f32.f16.f16.f32 "
        "{%0,%1,%2,%3}, {%4,%5,%6,%7}, {%8,%9}, {%0,%1,%2,%3};"
        : "+f"(c[0]), "+f"(c[1]), "+f"(c[2]), "+f"(c[3])
        : "r"(a[0]), "r"(a[1]), "r"(a[2]), "r"(a[3]), "r"(b0), "r"(b1));
}
__device__ __forceinline__ void ldsm4(uint32_t* r, uint32_t addr) {
    asm volatile("ldmatrix.sync.aligned.m8n8.x4.shared.b16 {%0,%1,%2,%3}, [%4];"
                 : "=r"(r[0]), "=r"(r[1]), "=r"(r[2]), "=r"(r[3]) : "r"(addr));
}
__device__ __forceinline__ void ldsm4t(uint32_t* r, uint32_t addr) {
    asm volatile("ldmatrix.sync.aligned.m8n8.x4.trans.shared.b16 {%0,%1,%2,%3}, [%4];"
                 : "=r"(r[0]), "=r"(r[1]), "=r"(r[2]), "=r"(r[3]) : "r"(addr));
}
#define CPA(s, g) \
    asm volatile("cp.async.cg.shared.global [%0], [%1], 16;" :: "r"(s), "l"(g) : "memory")
#define CPC() asm volatile("cp.async.commit_group;" ::: "memory")
#define CPW0() asm volatile("cp.async.wait_group 0;" ::: "memory")
#define CPW1() asm volatile("cp.async.wait_group 1;" ::: "memory")

__device__ __forceinline__ float ex2f(float x) {
    float y; asm("ex2.approx.f32 %0, %1;" : "=f"(y) : "f"(x)); return y;
}
__device__ __forceinline__ uint32_t packh(float a, float b) {
    __half2 t = __floats2half2_rn(a, b);
    return *(uint32_t*)&t;
}
__device__ __forceinline__ void split2h(float a, float b,
                                        __half2& hi, __half2& lo) {
    __half ah = __float2half(a), bh = __float2half(b);
    hi.x = ah; hi.y = bh;
    lo.x = __float2half(a - __half2float(ah));
    lo.y = __float2half(b - __half2float(bh));
}

// ---------------------------------------------------------------------------
// Prep kernels
// ---------------------------------------------------------------------------
__global__ void cvt16_kernel(const float* __restrict__ s,
                             __half* __restrict__ d, int n) {
    int i = blockIdx.x * blockDim.x + threadIdx.x;
    if (i < n) d[i] = __float2half(s[i]);
}
// W [K][N] f32 -> Th/Tl [N][K] fp16 hi/lo
__global__ void tsplit_kernel(const float* __restrict__ W,
                              __half* __restrict__ Th,
                              __half* __restrict__ Tl, int K, int N) {
    __shared__ float t[32][33];
    int n0 = blockIdx.x * 32, k0 = blockIdx.y * 32;
    int tx = threadIdx.x & 31, ty = threadIdx.x >> 5;
#pragma unroll
    for (int r = 0; r < 32; r += 8)
        t[ty + r][tx] = W[(size_t)(k0 + ty + r) * N + n0 + tx];
    __syncthreads();
#pragma unroll
    for (int r = 0; r < 32; r += 8) {
        float v = t[tx][ty + r];
        int n = n0 + ty + r, k = k0 + tx;
        __half vh = __float2half(v);
        Th[(size_t)n * K + k] = vh;
        Tl[(size_t)n * K + k] = __float2half(v - __half2float(vh));
    }
}

// ---------------------------------------------------------------------------
// fp16 2-pass HMMA GEMM:  C = A[M,K] @ (Bh+Bl)^T[N,K] + bias
// A single fp16, B split hi/lo. 3-stage cp.async pipeline (wait_group 1).
// MODE 0: f32 out + bias. MODE 1: fused QKV epilogue (fp16 per-head, Q scaled).
// ---------------------------------------------------------------------------
#define G_TILE 10240        // 128 * 40 * 2 bytes
#define G_STAGE (3 * G_TILE)
#define G_SMEM (3 * G_STAGE)   // 92160

template <int MODE>
__global__ __launch_bounds__(256, 2)
void gemm3(const __half* __restrict__ A,
           const __half* __restrict__ Bh,
           const __half* __restrict__ Bl,
           const float* __restrict__ bias,
           float* __restrict__ C, int M, int N, int K) {
    extern __shared__ __align__(16) char dsm[];
    const uint32_t uS = (uint32_t)__cvta_generic_to_shared(dsm);
    const int tid = threadIdx.x, lane = tid & 31, wid = tid >> 5;
    const int wm = wid >> 1, wn = wid & 1;
    const int m0 = blockIdx.y * 128, n0 = blockIdx.x * 128;

    float acc[2][8][4] = {};
    const int kch = K >> 5;

    auto issue = [&](int chunk) {
        const int kk = chunk << 5;
        const uint32_t sb = uS + (chunk % 3) * G_STAGE;
#pragma unroll
        for (int r = 0; r < 6; r++) {
            const int t = r >> 1;                    // 0=A 1=Bh 2=Bl
            const int local = ((r & 1) << 8) + tid;  // 0..511
            const int row = local >> 2, c = local & 3;
            const __half* src = (t == 0) ? A : (t == 1) ? Bh : Bl;
            const int rbase = (t == 0) ? m0 : n0;
            CPA(sb + t * G_TILE + row * 80 + c * 16,
                src + (size_t)(rbase + row) * K + kk + c * 8);
        }
        CPC();
    };

    issue(0);
    issue(1);
    for (int chunk = 0; chunk < kch; ++chunk) {
        CPW1();            // stage `chunk` complete (≤1 group left in flight)
        __syncthreads();   // also: all warps done with stage being overwritten
        if (chunk + 2 < kch) issue(chunk + 2);
        const uint32_t sb = uS + (chunk % 3) * G_STAGE;
        const uint32_t bA = sb;
        const uint32_t bBh = sb + G_TILE, bBl = sb + 2 * G_TILE;
#pragma unroll
        for (int ks = 0; ks < 2; ks++) {
            uint32_t af[2][4];
#pragma unroll
            for (int mt = 0; mt < 2; mt++) {
                int row = wm * 32 + mt * 16 + (lane & 15);
                int col = ks * 16 + ((lane >> 4) << 3);
                ldsm4(af[mt], bA + (row * 40 + col) * 2);
            }
#pragma unroll
            for (int np = 0; np < 4; np++) {
                uint32_t bh4[4], bl4[4];
                int n = wn * 64 + np * 16 + ((lane >> 4) << 3) + (lane & 7);
                int k = ks * 16 + (((lane >> 3) & 1) << 3);
                ldsm4(bh4, bBh + (n * 40 + k) * 2);
                ldsm4(bl4, bBl + (n * 40 + k) * 2);
#pragma unroll
                for (int mt = 0; mt < 2; mt++) {
                    mma16816h(acc[mt][2 * np], af[mt], bh4[0], bh4[1]);
                    mma16816h(acc[mt][2 * np + 1], af[mt], bh4[2], bh4[3]);
                    mma16816h(acc[mt][2 * np], af[mt], bl4[0], bl4[1]);
                    mma16816h(acc[mt][2 * np + 1], af[mt], bl4[2], bl4[3]);
                }
            }
        }
    }

    if (MODE == 0) {
#pragma unroll
        for (int mt = 0; mt < 2; mt++) {
            int r0 = m0 + wm * 32 + mt * 16 + (lane >> 2);
#pragma unroll
            for (int nt = 0; nt < 8; nt++) {
                int c = n0 + wn * 64 + nt * 8 + ((lane & 3) << 1);
                float b0 = bias[c], b1 = bias[c + 1];
                *(float2*)&C[(size_t)r0 * N + c] =
                    make_float2(acc[mt][nt][0] + b0, acc[mt][nt][1] + b1);
                *(float2*)&C[(size_t)(r0 + 8) * N + c] =
                    make_float2(acc[mt][nt][2] + b0, acc[mt][nt][3] + b1);
            }
        }
    } else {
        // fused QKV epilogue: bias, per-head layout, all single fp16 (Q scaled)
#pragma unroll
        for (int nt = 0; nt < 8; nt++) {
            int c = n0 + wn * 64 + nt * 8 + ((lane & 3) << 1);
            int sel = c >> 10;        // 0=Q 1=K 2=V
            int cc = c & 1023;
            int h = cc >> 6, d = cc & 63;
            float scl = (sel == 0) ? QSCALE : 1.0f;
            __half* dst = (sel == 0) ? g_q16 : (sel == 1) ? g_k16 : g_v16;
            float b0 = bias[c], b1 = bias[c + 1];
#pragma unroll
            for (int mt = 0; mt < 2; mt++) {
                int r0 = m0 + wm * 32 + mt * 16 + (lane >> 2);
#pragma unroll
                for (int half = 0; half < 2; half++) {
                    int r = r0 + half * 8;
                    float v0 = (acc[mt][nt][2 * half] + b0) * scl;
                    float v1 = (acc[mt][nt][2 * half + 1] + b1) * scl;
                    size_t o = ((size_t)h * LQ + r) * 64 + d;
                    *(__half2*)&dst[o] = __floats2half2_rn(v0, v1);
                }
            }
        }
    }
}

// ---------------------------------------------------------------------------
// Full-fp16 HMMA flash attention, causal, base-2 online softmax.
// 128 threads (4 warps x 16 q-rows = 64-row q-tile) per head.
// Single-pass QK^T and PV. K|V tiles per stage, 2-stage cp.async.
// ---------------------------------------------------------------------------
#define FT_ST 72
#define FT_TILE (64 * FT_ST * 2)   // 9216
#define FT_STAGE (2 * FT_TILE)     // 18432 (K, V)
#define FT_SMEM (2 * FT_STAGE)     // 36864

__global__ __launch_bounds__(128)
void flash_mma() {
    const int h = blockIdx.y;
    const int qt = (int)gridDim.x - 1 - (int)blockIdx.x; // heavy tiles first
    const int tid = threadIdx.x, lane = tid & 31, wid = tid >> 5;
    extern __shared__ __align__(16) char sm[];
    const uint32_t u0 = (uint32_t)__cvta_generic_to_shared(sm);
    const size_t hbase = (size_t)h * LQ * HDIM;

    // ---- Q fragments (fp16, single) straight from gmem ----
    const int qrow = qt * 64 + wid * 16 + (lane >> 2);
    uint32_t qh[4][4];
#pragma unroll
    for (int ks = 0; ks < 4; ks++) {
        int col = ks * 16 + ((lane & 3) << 1);
        size_t b00 = hbase + (size_t)qrow * 64 + col;
        qh[ks][0] = *(const uint32_t*)&g_q16[b00];
        qh[ks][1] = *(const uint32_t*)&g_q16[b00 + 8 * 64];
        qh[ks][2] = *(const uint32_t*)&g_q16[b00 + 8];
        qh[ks][3] = *(const uint32_t*)&g_q16[b00 + 8 * 64 + 8];
    }

    auto issue = [&](int kt) {
        const uint32_t sb = u0 + (kt & 1) * FT_STAGE;
#pragma unroll
        for (int r = 0; r < 8; r++) {
            const int t = r >> 2;                    // 0=K 1=V
            const int local = ((r & 3) << 7) + tid;  // 0..511
            const int row = local >> 3, c = local & 7;
            const __half* src = (t == 0) ? g_k16 : g_v16;
            CPA(sb + t * FT_TILE + row * (FT_ST * 2) + c * 16,
                src + hbase + (size_t)(kt * 64 + row) * 64 + c * 8);
        }
        CPC();
    };

    float o[8][4] = {};
    float m0 = -1e30f, m1 = -1e30f, l0 = 0.f, l1 = 0.f;
    const int grow0 = qrow;

    issue(0);
    for (int kt = 0; kt <= qt; ++kt) {
        CPW0();
        __syncthreads();
        if (kt < qt) issue(kt + 1);
        const uint32_t sb = u0 + (kt & 1) * FT_STAGE;
        const uint32_t uK = sb, uV = sb + FT_TILE;

        // ---- S = Q K^T (single fp16 pass) ----
        float s[8][4] = {};
#pragma unroll
        for (int ks = 0; ks < 4; ks++) {
#pragma unroll
            for (int np = 0; np < 4; np++) {
                uint32_t b4[4];
                int n = np * 16 + ((lane >> 4) << 3) + (lane & 7);
                int k = ks * 16 + (((lane >> 3) & 1) << 3);
                ldsm4(b4, uK + (n * FT_ST + k) * 2);
                mma16816h(s[2 * np], qh[ks], b4[0], b4[1]);
                mma16816h(s[2 * np + 1], qh[ks], b4[2], b4[3]);
            }
        }

        if (kt == qt) {  // causal mask on diagonal tile
#pragma unroll
            for (int nt = 0; nt < 8; nt++) {
                int c0 = kt * 64 + nt * 8 + ((lane & 3) << 1);
                if (c0 > grow0) s[nt][0] = -1e30f;
                if (c0 + 1 > grow0) s[nt][1] = -1e30f;
                if (c0 > grow0 + 8) s[nt][2] = -1e30f;
                if (c0 + 1 > grow0 + 8) s[nt][3] = -1e30f;
            }
        }

        // ---- online softmax (base-2) ----
        float mx0 = -1e30f, mx1 = -1e30f;
#pragma unroll
        for (int nt = 0; nt < 8; nt++) {
            mx0 = fmaxf(mx0, fmaxf(s[nt][0], s[nt][1]));
            mx1 = fmaxf(mx1, fmaxf(s[nt][2], s[nt][3]));
        }
        mx0 = fmaxf(mx0, __shfl_xor_sync(0xffffffffu, mx0, 1));
        mx0 = fmaxf(mx0, __shfl_xor_sync(0xffffffffu, mx0, 2));
        mx1 = fmaxf(mx1, __shfl_xor_sync(0xffffffffu, mx1, 1));
        mx1 = fmaxf(mx1, __shfl_xor_sync(0xffffffffu, mx1, 2));
        float mn0 = fmaxf(m0, mx0), mn1 = fmaxf(m1, mx1);
        float corr0 = ex2f(m0 - mn0), corr1 = ex2f(m1 - mn1);
        m0 = mn0; m1 = mn1;
        float ps0 = 0.f, ps1 = 0.f;
#pragma unroll
        for (int nt = 0; nt < 8; nt++) {
            s[nt][0] = ex2f(s[nt][0] - mn0);
            s[nt][1] = ex2f(s[nt][1] - mn0);
            s[nt][2] = ex2f(s[nt][2] - mn1);
            s[nt][3] = ex2f(s[nt][3] - mn1);
            ps0 += s[nt][0] + s[nt][1];
            ps1 += s[nt][2] + s[nt][3];
        }
        ps0 += __shfl_xor_sync(0xffffffffu, ps0, 1);
        ps0 += __shfl_xor_sync(0xffffffffu, ps0, 2);
        ps1 += __shfl_xor_sync(0xffffffffu, ps1, 1);
        ps1 += __shfl_xor_sync(0xffffffffu, ps1, 2);
        l0 = l0 * corr0 + ps0;
        l1 = l1 * corr1 + ps1;
#pragma unroll
        for (int nt = 0; nt < 8; nt++) {
            o[nt][0] *= corr0; o[nt][1] *= corr0;
            o[nt][2] *= corr1; o[nt][3] *= corr1;
        }

        // ---- O += P V (single fp16 pass) ----
#pragma unroll
        for (int ks = 0; ks < 4; ks++) {
            uint32_t a[4];
            a[0] = packh(s[2 * ks][0], s[2 * ks][1]);
            a[1] = packh(s[2 * ks][2], s[2 * ks][3]);
            a[2] = packh(s[2 * ks + 1][0], s[2 * ks + 1][1]);
            a[3] = packh(s[2 * ks + 1][2], s[2 * ks + 1][3]);
            int row = ks * 16 + ((lane >> 3) & 1) * 8 + (lane & 7);
#pragma unroll
            for (int np = 0; np < 4; np++) {
                uint32_t b4[4];
                int dc = np * 16 + ((lane >> 4) << 3);
                ldsm4t(b4, uV + (row * FT_ST + dc) * 2);
                mma16816h(o[2 * np], a, b4[0], b4[1]);
                mma16816h(o[2 * np + 1], a, b4[2], b4[3]);
            }
        }
    }

    // ---- epilogue: normalize, write single fp16 [L][C] ----
    float inv0 = 1.f / l0, inv1 = 1.f / l1;
#pragma unroll
    for (int nt = 0; nt < 8; nt++) {
        int c = h * 64 + nt * 8 + ((lane & 3) << 1);
        *(__half2*)&g_a16[(size_t)grow0 * CDIM + c] =
            __floats2half2_rn(o[nt][0] * inv0, o[nt][1] * inv0);
        *(__half2*)&g_a16[(size_t)(grow0 + 8) * CDIM + c] =
            __floats2half2_rn(o[nt][2] * inv1, o[nt][3] * inv1);
    }
}

// ---------------------------------------------------------------------------
// Launch
// ---------------------------------------------------------------------------
extern "C" void kernel_launch(void* const* d_in, const int* in_sizes, int n_in,
                              void* d_out, int out_size) {
    (void)in_sizes; (void)n_in; (void)out_size;
    const float* x = (const float*)d_in[0];
    const float* Wqkv = (const float*)d_in[1];
    const float* bqkv = (const float*)d_in[2];
    const float* Wout = (const float*)d_in[3];
    const float* bout = (const float*)d_in[4];
    float* out = (float*)d_out;

    __half *x16, *a16, *wqh, *wql, *woh, *wol;
    cudaGetSymbolAddress((void**)&x16, g_x16);
    cudaGetSymbolAddress((void**)&a16, g_a16);
    cudaGetSymbolAddress((void**)&wqh, g_wqh16);
    cudaGetSymbolAddress((void**)&wql, g_wql16);
    cudaGetSymbolAddress((void**)&woh, g_woh16);
    cudaGetSymbolAddress((void**)&wol, g_wol16);

    static int attr_set = 0;
    if (!attr_set) {
        cudaFuncSetAttribute(gemm3<0>, cudaFuncAttributeMaxDynamicSharedMemorySize, G_SMEM);
        cudaFuncSetAttribute(gemm3<1>, cudaFuncAttributeMaxDynamicSharedMemorySize, G_SMEM);
        cudaFuncSetAttribute(flash_mma, cudaFuncAttributeMaxDynamicSharedMemorySize, FT_SMEM);
        attr_set = 1;
    }

    // prep: X -> fp16, transpose-split weights fp16 hi/lo
    cvt16_kernel<<<(LQ * CDIM) / 256, 256>>>(x, x16, LQ * CDIM);
    tsplit_kernel<<<dim3(C3 / 32, CDIM / 32), 256>>>(Wqkv, wqh, wql, CDIM, C3);
    tsplit_kernel<<<dim3(CDIM / 32, CDIM / 32), 256>>>(Wout, woh, wol, CDIM, CDIM);

    // 1) QKV projection (fp16 2-pass, 3-stage pipe) + fused per-head epilogue
    gemm3<1><<<dim3(C3 / 128, LQ / 128), 256, G_SMEM>>>(
        x16, wqh, wql, bqkv, nullptr, LQ, C3, CDIM);

    // 2) causal flash attention (full fp16, single-pass QK/PV)
    flash_mma<<<dim3(LQ / 64, NHEADS), 128, FT_SMEM>>>();

    // 3) output projection (fp16 2-pass, 3-stage pipe)
    gemm3<0><<<dim3(CDIM / 128, LQ / 128), 256, G_SMEM>>>(
        a16, woh, wol, bout, out, LQ, CDIM, CDIM);
}

// round 14
// speedup vs baseline: 1.5563x; 1.5563x over previous
#include <cuda_runtime.h>
#include <cuda_bf16.h>
#include <cuda_fp16.h>
#include <math.h>
#include <stdint.h>

#define LQ 4096
#define CDIM 1024
#define NHEADS 16
#define HDIM 64
#define C3 3072
// 0.125 * log2(e): fold softmax base-2 conversion into Q scaling
#define QSCALE 0.18033688011112042f

// ---------------------------------------------------------------------------
// Device-global scratch (all fp16)
// ---------------------------------------------------------------------------
__device__ __half g_x16[LQ * CDIM];                               // X single
__device__ __half g_a16[LQ * CDIM];                               // attn out single
__device__ __half g_wqh16[C3 * CDIM], g_wql16[C3 * CDIM];         // [N][K] hi/lo
__device__ __half g_woh16[CDIM * CDIM], g_wol16[CDIM * CDIM];     // [N][K] hi/lo
__device__ __half g_q16[NHEADS * LQ * HDIM];                      // Q*QSCALE single
__device__ __half g_k16[NHEADS * LQ * HDIM];                      // K single
__device__ __half g_v16[NHEADS * LQ * HDIM];                      // V single

// ---------------------------------------------------------------------------
// Warp-MMA helpers
// ---------------------------------------------------------------------------
__device__ __forceinline__ void mma16816h(float* c, const uint32_t* a,
                                          uint32_t b0, uint32_t b1) {
    asm volatile(
        "mma.sync.aligned.m16n8k16.row.col.f32.f16.f16.f32 "
        "{%0,%1,%2,%3}, {%4,%5,%6,%7}, {%8,%9}, {%0,%1,%2,%3};"
        : "+f"(c[0]), "+f"(c[1]), "+f"(c[2]), "+f"(c[3])
        : "r"(a[0]), "r"(a[1]), "r"(a[2]), "r"(a[3]), "r"(b0), "r"(b1));
}
__device__ __forceinline__ void ldsm4(uint32_t* r, uint32_t addr) {
    asm volatile("ldmatrix.sync.aligned.m8n8.x4.shared.b16 {%0,%1,%2,%3}, [%4];"
                 : "=r"(r[0]), "=r"(r[1]), "=r"(r[2]), "=r"(r[3]) : "r"(addr));
}
__device__ __forceinline__ void ldsm4t(uint32_t* r, uint32_t addr) {
    asm volatile("ldmatrix.sync.aligned.m8n8.x4.trans.shared.b16 {%0,%1,%2,%3}, [%4];"
                 : "=r"(r[0]), "=r"(r[1]), "=r"(r[2]), "=r"(r[3]) : "r"(addr));
}
#define CPA(s, g) \
    asm volatile("cp.async.cg.shared.global [%0], [%1], 16;" :: "r"(s), "l"(g) : "memory")
#define CPC() asm volatile("cp.async.commit_group;" ::: "memory")
#define CPW0() asm volatile("cp.async.wait_group 0;" ::: "memory")

__device__ __forceinline__ float ex2f(float x) {
    float y; asm("ex2.approx.f32 %0, %1;" : "=f"(y) : "f"(x)); return y;
}
__device__ __forceinline__ uint32_t packh(float a, float b) {
    __half2 t = __floats2half2_rn(a, b);
    return *(uint32_t*)&t;
}
__device__ __forceinline__ void split2h(float a, float b,
                                        __half2& hi, __half2& lo) {
    __half ah = __float2half(a), bh = __float2half(b);
    hi.x = ah; hi.y = bh;
    lo.x = __float2half(a - __half2float(ah));
    lo.y = __float2half(b - __half2float(bh));
}

// ---------------------------------------------------------------------------
// Prep kernels
// ---------------------------------------------------------------------------
__global__ void cvt16_kernel(const float* __restrict__ s,
                             __half* __restrict__ d, int n) {
    int i = blockIdx.x * blockDim.x + threadIdx.x;
    if (i < n) d[i] = __float2half(s[i]);
}
// W [K][N] f32 -> Th/Tl [N][K] fp16 hi/lo
__global__ void tsplit_kernel(const float* __restrict__ W,
                              __half* __restrict__ Th,
                              __half* __restrict__ Tl, int K, int N) {
    __shared__ float t[32][33];
    int n0 = blockIdx.x * 32, k0 = blockIdx.y * 32;
    int tx = threadIdx.x & 31, ty = threadIdx.x >> 5;
#pragma unroll
    for (int r = 0; r < 32; r += 8)
        t[ty + r][tx] = W[(size_t)(k0 + ty + r) * N + n0 + tx];
    __syncthreads();
#pragma unroll
    for (int r = 0; r < 32; r += 8) {
        float v = t[tx][ty + r];
        int n = n0 + ty + r, k = k0 + tx;
        __half vh = __float2half(v);
        Th[(size_t)n * K + k] = vh;
        Tl[(size_t)n * K + k] = __float2half(v - __half2float(vh));
    }
}

// ---------------------------------------------------------------------------
// fp16 2-pass HMMA GEMM:  C = A[M,K] @ (Bh+Bl)^T[N,K] + bias
// A single fp16, B split hi/lo. 2-stage cp.async (R11 config — known best).
// MODE 0: f32 out + bias. MODE 1: fused QKV epilogue (fp16 per-head, Q scaled).
// ---------------------------------------------------------------------------
#define G_TILE 10240        // 128 * 40 * 2 bytes
#define G_STAGE (3 * G_TILE)
#define G_SMEM (2 * G_STAGE)   // 61440

template <int MODE>
__global__ __launch_bounds__(256, 2)
void gemm3(const __half* __restrict__ A,
           const __half* __restrict__ Bh,
           const __half* __restrict__ Bl,
           const float* __restrict__ bias,
           float* __restrict__ C, int M, int N, int K) {
    extern __shared__ __align__(16) char dsm[];
    const uint32_t uS = (uint32_t)__cvta_generic_to_shared(dsm);
    const int tid = threadIdx.x, lane = tid & 31, wid = tid >> 5;
    const int wm = wid >> 1, wn = wid & 1;
    const int m0 = blockIdx.y * 128, n0 = blockIdx.x * 128;

    float acc[2][8][4] = {};
    const int kch = K >> 5;

    auto issue = [&](int chunk) {
        const int kk = chunk << 5;
        const uint32_t sb = uS + (chunk & 1) * G_STAGE;
#pragma unroll
        for (int r = 0; r < 6; r++) {
            const int t = r >> 1;                    // 0=A 1=Bh 2=Bl
            const int local = ((r & 1) << 8) + tid;  // 0..511
            const int row = local >> 2, c = local & 3;
            const __half* src = (t == 0) ? A : (t == 1) ? Bh : Bl;
            const int rbase = (t == 0) ? m0 : n0;
            CPA(sb + t * G_TILE + row * 80 + c * 16,
                src + (size_t)(rbase + row) * K + kk + c * 8);
        }
        CPC();
    };

    issue(0);
    for (int chunk = 0; chunk < kch; ++chunk) {
        CPW0();
        __syncthreads();
        if (chunk + 1 < kch) issue(chunk + 1);
        const uint32_t sb = uS + (chunk & 1) * G_STAGE;
        const uint32_t bA = sb;
        const uint32_t bBh = sb + G_TILE, bBl = sb + 2 * G_TILE;
#pragma unroll
        for (int ks = 0; ks < 2; ks++) {
            uint32_t af[2][4];
#pragma unroll
            for (int mt = 0; mt < 2; mt++) {
                int row = wm * 32 + mt * 16 + (lane & 15);
                int col = ks * 16 + ((lane >> 4) << 3);
                ldsm4(af[mt], bA + (row * 40 + col) * 2);
            }
#pragma unroll
            for (int np = 0; np < 4; np++) {
                uint32_t bh4[4], bl4[4];
                int n = wn * 64 + np * 16 + ((lane >> 4) << 3) + (lane & 7);
                int k = ks * 16 + (((lane >> 3) & 1) << 3);
                ldsm4(bh4, bBh + (n * 40 + k) * 2);
                ldsm4(bl4, bBl + (n * 40 + k) * 2);
#pragma unroll
                for (int mt = 0; mt < 2; mt++) {
                    mma16816h(acc[mt][2 * np], af[mt], bh4[0], bh4[1]);
                    mma16816h(acc[mt][2 * np + 1], af[mt], bh4[2], bh4[3]);
                    mma16816h(acc[mt][2 * np], af[mt], bl4[0], bl4[1]);
                    mma16816h(acc[mt][2 * np + 1], af[mt], bl4[2], bl4[3]);
                }
            }
        }
    }

    if (MODE == 0) {
#pragma unroll
        for (int mt = 0; mt < 2; mt++) {
            int r0 = m0 + wm * 32 + mt * 16 + (lane >> 2);
#pragma unroll
            for (int nt = 0; nt < 8; nt++) {
                int c = n0 + wn * 64 + nt * 8 + ((lane & 3) << 1);
                float b0 = bias[c], b1 = bias[c + 1];
                *(float2*)&C[(size_t)r0 * N + c] =
                    make_float2(acc[mt][nt][0] + b0, acc[mt][nt][1] + b1);
                *(float2*)&C[(size_t)(r0 + 8) * N + c] =
                    make_float2(acc[mt][nt][2] + b0, acc[mt][nt][3] + b1);
            }
        }
    } else {
        // fused QKV epilogue: bias, per-head layout, all single fp16 (Q scaled)
#pragma unroll
        for (int nt = 0; nt < 8; nt++) {
            int c = n0 + wn * 64 + nt * 8 + ((lane & 3) << 1);
            int sel = c >> 10;        // 0=Q 1=K 2=V
            int cc = c & 1023;
            int h = cc >> 6, d = cc & 63;
            float scl = (sel == 0) ? QSCALE : 1.0f;
            __half* dst = (sel == 0) ? g_q16 : (sel == 1) ? g_k16 : g_v16;
            float b0 = bias[c], b1 = bias[c + 1];
#pragma unroll
            for (int mt = 0; mt < 2; mt++) {
                int r0 = m0 + wm * 32 + mt * 16 + (lane >> 2);
#pragma unroll
                for (int half = 0; half < 2; half++) {
                    int r = r0 + half * 8;
                    float v0 = (acc[mt][nt][2 * half] + b0) * scl;
                    float v1 = (acc[mt][nt][2 * half + 1] + b1) * scl;
                    size_t o = ((size_t)h * LQ + r) * 64 + d;
                    *(__half2*)&dst[o] = __floats2half2_rn(v0, v1);
                }
            }
        }
    }
}

// ---------------------------------------------------------------------------
// Full-fp16 HMMA flash attention, causal, base-2 online softmax.
// 128 threads (4 warps x 16 q-rows = 64-row q-tile) per head.
// Single-pass QK^T and PV. K|V tiles per stage, 2-stage cp.async.
// ---------------------------------------------------------------------------
#define FT_ST 72
#define FT_TILE (64 * FT_ST * 2)   // 9216
#define FT_STAGE (2 * FT_TILE)     // 18432 (K, V)
#define FT_SMEM (2 * FT_STAGE)     // 36864

__global__ __launch_bounds__(128)
void flash_mma() {
    const int h = blockIdx.y;
    const int qt = (int)gridDim.x - 1 - (int)blockIdx.x; // heavy tiles first
    const int tid = threadIdx.x, lane = tid & 31, wid = tid >> 5;
    extern __shared__ __align__(16) char sm[];
    const uint32_t u0 = (uint32_t)__cvta_generic_to_shared(sm);
    const size_t hbase = (size_t)h * LQ * HDIM;

    // ---- Q fragments (fp16, single) straight from gmem ----
    const int qrow = qt * 64 + wid * 16 + (lane >> 2);
    uint32_t qh[4][4];
#pragma unroll
    for (int ks = 0; ks < 4; ks++) {
        int col = ks * 16 + ((lane & 3) << 1);
        size_t b00 = hbase + (size_t)qrow * 64 + col;
        qh[ks][0] = *(const uint32_t*)&g_q16[b00];
        qh[ks][1] = *(const uint32_t*)&g_q16[b00 + 8 * 64];
        qh[ks][2] = *(const uint32_t*)&g_q16[b00 + 8];
        qh[ks][3] = *(const uint32_t*)&g_q16[b00 + 8 * 64 + 8];
    }

    auto issue = [&](int kt) {
        const uint32_t sb = u0 + (kt & 1) * FT_STAGE;
#pragma unroll
        for (int r = 0; r < 8; r++) {
            const int t = r >> 2;                    // 0=K 1=V
            const int local = ((r & 3) << 7) + tid;  // 0..511
            const int row = local >> 3, c = local & 7;
            const __half* src = (t == 0) ? g_k16 : g_v16;
            CPA(sb + t * FT_TILE + row * (FT_ST * 2) + c * 16,
                src + hbase + (size_t)(kt * 64 + row) * 64 + c * 8);
        }
        CPC();
    };

    float o[8][4] = {};
    float m0 = -1e30f, m1 = -1e30f, l0 = 0.f, l1 = 0.f;
    const int grow0 = qrow;

    issue(0);
    for (int kt = 0; kt <= qt; ++kt) {
        CPW0();
        __syncthreads();
        if (kt < qt) issue(kt + 1);
        const uint32_t sb = u0 + (kt & 1) * FT_STAGE;
        const uint32_t uK = sb, uV = sb + FT_TILE;

        // ---- S = Q K^T (single fp16 pass) ----
        float s[8][4] = {};
#pragma unroll
        for (int ks = 0; ks < 4; ks++) {
#pragma unroll
            for (int np = 0; np < 4; np++) {
                uint32_t b4[4];
                int n = np * 16 + ((lane >> 4) << 3) + (lane & 7);
                int k = ks * 16 + (((lane >> 3) & 1) << 3);
                ldsm4(b4, uK + (n * FT_ST + k) * 2);
                mma16816h(s[2 * np], qh[ks], b4[0], b4[1]);
                mma16816h(s[2 * np + 1], qh[ks], b4[2], b4[3]);
            }
        }

        if (kt == qt) {  // causal mask on diagonal tile
#pragma unroll
            for (int nt = 0; nt < 8; nt++) {
                int c0 = kt * 64 + nt * 8 + ((lane & 3) << 1);
                if (c0 > grow0) s[nt][0] = -1e30f;
                if (c0 + 1 > grow0) s[nt][1] = -1e30f;
                if (c0 > grow0 + 8) s[nt][2] = -1e30f;
                if (c0 + 1 > grow0 + 8) s[nt][3] = -1e30f;
            }
        }

        // ---- online softmax (base-2) ----
        float mx0 = -1e30f, mx1 = -1e30f;
#pragma unroll
        for (int nt = 0; nt < 8; nt++) {
            mx0 = fmaxf(mx0, fmaxf(s[nt][0], s[nt][1]));
            mx1 = fmaxf(mx1, fmaxf(s[nt][2], s[nt][3]));
        }
        mx0 = fmaxf(mx0, __shfl_xor_sync(0xffffffffu, mx0, 1));
        mx0 = fmaxf(mx0, __shfl_xor_sync(0xffffffffu, mx0, 2));
        mx1 = fmaxf(mx1, __shfl_xor_sync(0xffffffffu, mx1, 1));
        mx1 = fmaxf(mx1, __shfl_xor_sync(0xffffffffu, mx1, 2));
        float mn0 = fmaxf(m0, mx0), mn1 = fmaxf(m1, mx1);
        float corr0 = ex2f(m0 - mn0), corr1 = ex2f(m1 - mn1);
        m0 = mn0; m1 = mn1;
        float ps0 = 0.f, ps1 = 0.f;
#pragma unroll
        for (int nt = 0; nt < 8; nt++) {
            s[nt][0] = ex2f(s[nt][0] - mn0);
            s[nt][1] = ex2f(s[nt][1] - mn0);
            s[nt][2] = ex2f(s[nt][2] - mn1);
            s[nt][3] = ex2f(s[nt][3] - mn1);
            ps0 += s[nt][0] + s[nt][1];
            ps1 += s[nt][2] + s[nt][3];
        }
        ps0 += __shfl_xor_sync(0xffffffffu, ps0, 1);
        ps0 += __shfl_xor_sync(0xffffffffu, ps0, 2);
        ps1 += __shfl_xor_sync(0xffffffffu, ps1, 1);
        ps1 += __shfl_xor_sync(0xffffffffu, ps1, 2);
        l0 = l0 * corr0 + ps0;
        l1 = l1 * corr1 + ps1;
#pragma unroll
        for (int nt = 0; nt < 8; nt++) {
            o[nt][0] *= corr0; o[nt][1] *= corr0;
            o[nt][2] *= corr1; o[nt][3] *= corr1;
        }

        // ---- O += P V (single fp16 pass) ----
#pragma unroll
        for (int ks = 0; ks < 4; ks++) {
            uint32_t a[4];
            a[0] = packh(s[2 * ks][0], s[2 * ks][1]);
            a[1] = packh(s[2 * ks][2], s[2 * ks][3]);
            a[2] = packh(s[2 * ks + 1][0], s[2 * ks + 1][1]);
            a[3] = packh(s[2 * ks + 1][2], s[2 * ks + 1][3]);
            int row = ks * 16 + ((lane >> 3) & 1) * 8 + (lane & 7);
#pragma unroll
            for (int np = 0; np < 4; np++) {
                uint32_t b4[4];
                int dc = np * 16 + ((lane >> 4) << 3);
                ldsm4t(b4, uV + (row * FT_ST + dc) * 2);
                mma16816h(o[2 * np], a, b4[0], b4[1]);
                mma16816h(o[2 * np + 1], a, b4[2], b4[3]);
            }
        }
    }

    // ---- epilogue: normalize, write single fp16 [L][C] ----
    float inv0 = 1.f / l0, inv1 = 1.f / l1;
#pragma unroll
    for (int nt = 0; nt < 8; nt++) {
        int c = h * 64 + nt * 8 + ((lane & 3) << 1);
        *(__half2*)&g_a16[(size_t)grow0 * CDIM + c] =
            __floats2half2_rn(o[nt][0] * inv0, o[nt][1] * inv0);
        *(__half2*)&g_a16[(size_t)(grow0 + 8) * CDIM + c] =
            __floats2half2_rn(o[nt][2] * inv1, o[nt][3] * inv1);
    }
}

// ---------------------------------------------------------------------------
// Launch
// ---------------------------------------------------------------------------
extern "C" void kernel_launch(void* const* d_in, const int* in_sizes, int n_in,
                              void* d_out, int out_size) {
    (void)in_sizes; (void)n_in; (void)out_size;
    const float* x = (const float*)d_in[0];
    const float* Wqkv = (const float*)d_in[1];
    const float* bqkv = (const float*)d_in[2];
    const float* Wout = (const float*)d_in[3];
    const float* bout = (const float*)d_in[4];
    float* out = (float*)d_out;

    __half *x16, *a16, *wqh, *wql, *woh, *wol;
    cudaGetSymbolAddress((void**)&x16, g_x16);
    cudaGetSymbolAddress((void**)&a16, g_a16);
    cudaGetSymbolAddress((void**)&wqh, g_wqh16);
    cudaGetSymbolAddress((void**)&wql, g_wql16);
    cudaGetSymbolAddress((void**)&woh, g_woh16);
    cudaGetSymbolAddress((void**)&wol, g_wol16);

    static int attr_set = 0;
    if (!attr_set) {
        cudaFuncSetAttribute(gemm3<0>, cudaFuncAttributeMaxDynamicSharedMemorySize, G_SMEM);
        cudaFuncSetAttribute(gemm3<1>, cudaFuncAttributeMaxDynamicSharedMemorySize, G_SMEM);
        cudaFuncSetAttribute(flash_mma, cudaFuncAttributeMaxDynamicSharedMemorySize, FT_SMEM);
        attr_set = 1;
    }

    // prep: X -> fp16, transpose-split weights fp16 hi/lo
    cvt16_kernel<<<(LQ * CDIM) / 256, 256>>>(x, x16, LQ * CDIM);
    tsplit_kernel<<<dim3(C3 / 32, CDIM / 32), 256>>>(Wqkv, wqh, wql, CDIM, C3);
    tsplit_kernel<<<dim3(CDIM / 32, CDIM / 32), 256>>>(Wout, woh, wol, CDIM, CDIM);

    // 1) QKV projection (fp16 2-pass, 2-stage pipe) + fused per-head epilogue
    gemm3<1><<<dim3(C3 / 128, LQ / 128), 256, G_SMEM>>>(
        x16, wqh, wql, bqkv, nullptr, LQ, C3, CDIM);

    // 2) causal flash attention (full fp16, single-pass QK/PV)
    flash_mma<<<dim3(LQ / 64, NHEADS), 128, FT_SMEM>>>();

    // 3) output projection (fp16 2-pass, 2-stage pipe)
    gemm3<0><<<dim3(CDIM / 128, LQ / 128), 256, G_SMEM>>>(
        a16, woh, wol, bout, out, LQ, CDIM, CDIM);
}

// round 15
// speedup vs baseline: 2.0796x; 1.3363x over previous
#include <cuda_runtime.h>
#include <cuda_bf16.h>
#include <cuda_fp16.h>
#include <math.h>
#include <stdint.h>

#define LQ 4096
#define CDIM 1024
#define NHEADS 16
#define HDIM 64
#define C3 3072
// 0.125 * log2(e): fold softmax base-2 conversion into Q scaling
#define QSCALE 0.18033688011112042f

// ---------------------------------------------------------------------------
// Device-global scratch (all fp16, all single precision-level)
// ---------------------------------------------------------------------------
__device__ __half g_x16[LQ * CDIM];                               // X
__device__ __half g_a16[LQ * CDIM];                               // attn out
__device__ __half g_wq16[C3 * CDIM];                              // Wqkv^T [N][K]
__device__ __half g_wo16[CDIM * CDIM];                            // Wout^T [N][K]
__device__ __half g_q16[NHEADS * LQ * HDIM];                      // Q*QSCALE
__device__ __half g_k16[NHEADS * LQ * HDIM];                      // K
__device__ __half g_v16[NHEADS * LQ * HDIM];                      // V

// ---------------------------------------------------------------------------
// Warp-MMA helpers
// ---------------------------------------------------------------------------
__device__ __forceinline__ void mma16816h(float* c, const uint32_t* a,
                                          uint32_t b0, uint32_t b1) {
    asm volatile(
        "mma.sync.aligned.m16n8k16.row.col.f32.f16.f16.f32 "
        "{%0,%1,%2,%3}, {%4,%5,%6,%7}, {%8,%9}, {%0,%1,%2,%3};"
        : "+f"(c[0]), "+f"(c[1]), "+f"(c[2]), "+f"(c[3])
        : "r"(a[0]), "r"(a[1]), "r"(a[2]), "r"(a[3]), "r"(b0), "r"(b1));
}
__device__ __forceinline__ void ldsm4(uint32_t* r, uint32_t addr) {
    asm volatile("ldmatrix.sync.aligned.m8n8.x4.shared.b16 {%0,%1,%2,%3}, [%4];"
                 : "=r"(r[0]), "=r"(r[1]), "=r"(r[2]), "=r"(r[3]) : "r"(addr));
}
__device__ __forceinline__ void ldsm4t(uint32_t* r, uint32_t addr) {
    asm volatile("ldmatrix.sync.aligned.m8n8.x4.trans.shared.b16 {%0,%1,%2,%3}, [%4];"
                 : "=r"(r[0]), "=r"(r[1]), "=r"(r[2]), "=r"(r[3]) : "r"(addr));
}
#define CPA(s, g) \
    asm volatile("cp.async.cg.shared.global [%0], [%1], 16;" :: "r"(s), "l"(g) : "memory")
#define CPC() asm volatile("cp.async.commit_group;" ::: "memory")
#define CPW0() asm volatile("cp.async.wait_group 0;" ::: "memory")

__device__ __forceinline__ float ex2f(float x) {
    float y; asm("ex2.approx.f32 %0, %1;" : "=f"(y) : "f"(x)); return y;
}
__device__ __forceinline__ uint32_t packh(float a, float b) {
    __half2 t = __floats2half2_rn(a, b);
    return *(uint32_t*)&t;
}

// ---------------------------------------------------------------------------
// Prep kernels
// ---------------------------------------------------------------------------
__global__ void cvt16_kernel(const float* __restrict__ s,
                             __half* __restrict__ d, int n) {
    int i = blockIdx.x * blockDim.x + threadIdx.x;
    if (i < n) d[i] = __float2half(s[i]);
}
// W [K][N] f32 -> T [N][K] fp16
__global__ void tcvt_kernel(const float* __restrict__ W,
                            __half* __restrict__ T, int K, int N) {
    __shared__ float t[32][33];
    int n0 = blockIdx.x * 32, k0 = blockIdx.y * 32;
    int tx = threadIdx.x & 31, ty = threadIdx.x >> 5;
#pragma unroll
    for (int r = 0; r < 32; r += 8)
        t[ty + r][tx] = W[(size_t)(k0 + ty + r) * N + n0 + tx];
    __syncthreads();
#pragma unroll
    for (int r = 0; r < 32; r += 8) {
        int n = n0 + ty + r, k = k0 + tx;
        T[(size_t)n * K + k] = __float2half(t[tx][ty + r]);
    }
}

// ---------------------------------------------------------------------------
// Single-pass fp16 HMMA GEMM:  C = A[M,K] @ B^T[N,K] + bias
// R11 skeleton (2-stage cp.async, 128-reg/2-CTA), Bl tile removed.
// MODE 0: f32 out + bias. MODE 1: fused QKV epilogue (fp16 per-head, Q scaled).
// ---------------------------------------------------------------------------
#define G_TILE 10240        // 128 * 40 * 2 bytes
#define G_STAGE (2 * G_TILE)
#define G_SMEM (2 * G_STAGE)   // 40960

template <int MODE>
__global__ __launch_bounds__(256, 2)
void gemm3(const __half* __restrict__ A,
           const __half* __restrict__ B,
           const float* __restrict__ bias,
           float* __restrict__ C, int M, int N, int K) {
    extern __shared__ __align__(16) char dsm[];
    const uint32_t uS = (uint32_t)__cvta_generic_to_shared(dsm);
    const int tid = threadIdx.x, lane = tid & 31, wid = tid >> 5;
    const int wm = wid >> 1, wn = wid & 1;
    const int m0 = blockIdx.y * 128, n0 = blockIdx.x * 128;

    float acc[2][8][4] = {};
    const int kch = K >> 5;

    auto issue = [&](int chunk) {
        const int kk = chunk << 5;
        const uint32_t sb = uS + (chunk & 1) * G_STAGE;
#pragma unroll
        for (int r = 0; r < 4; r++) {
            const int t = r >> 1;                    // 0=A 1=B
            const int local = ((r & 1) << 8) + tid;  // 0..511
            const int row = local >> 2, c = local & 3;
            const __half* src = (t == 0) ? A : B;
            const int rbase = (t == 0) ? m0 : n0;
            CPA(sb + t * G_TILE + row * 80 + c * 16,
                src + (size_t)(rbase + row) * K + kk + c * 8);
        }
        CPC();
    };

    issue(0);
    for (int chunk = 0; chunk < kch; ++chunk) {
        CPW0();
        __syncthreads();
        if (chunk + 1 < kch) issue(chunk + 1);
        const uint32_t sb = uS + (chunk & 1) * G_STAGE;
        const uint32_t bA = sb;
        const uint32_t bB = sb + G_TILE;
#pragma unroll
        for (int ks = 0; ks < 2; ks++) {
            uint32_t af[2][4];
#pragma unroll
            for (int mt = 0; mt < 2; mt++) {
                int row = wm * 32 + mt * 16 + (lane & 15);
                int col = ks * 16 + ((lane >> 4) << 3);
                ldsm4(af[mt], bA + (row * 40 + col) * 2);
            }
#pragma unroll
            for (int np = 0; np < 4; np++) {
                uint32_t b4[4];
                int n = wn * 64 + np * 16 + ((lane >> 4) << 3) + (lane & 7);
                int k = ks * 16 + (((lane >> 3) & 1) << 3);
                ldsm4(b4, bB + (n * 40 + k) * 2);
#pragma unroll
                for (int mt = 0; mt < 2; mt++) {
                    mma16816h(acc[mt][2 * np], af[mt], b4[0], b4[1]);
                    mma16816h(acc[mt][2 * np + 1], af[mt], b4[2], b4[3]);
                }
            }
        }
    }

    if (MODE == 0) {
#pragma unroll
        for (int mt = 0; mt < 2; mt++) {
            int r0 = m0 + wm * 32 + mt * 16 + (lane >> 2);
#pragma unroll
            for (int nt = 0; nt < 8; nt++) {
                int c = n0 + wn * 64 + nt * 8 + ((lane & 3) << 1);
                float b0 = bias[c], b1 = bias[c + 1];
                *(float2*)&C[(size_t)r0 * N + c] =
                    make_float2(acc[mt][nt][0] + b0, acc[mt][nt][1] + b1);
                *(float2*)&C[(size_t)(r0 + 8) * N + c] =
                    make_float2(acc[mt][nt][2] + b0, acc[mt][nt][3] + b1);
            }
        }
    } else {
        // fused QKV epilogue: bias, per-head layout, fp16 (Q scaled)
#pragma unroll
        for (int nt = 0; nt < 8; nt++) {
            int c = n0 + wn * 64 + nt * 8 + ((lane & 3) << 1);
            int sel = c >> 10;        // 0=Q 1=K 2=V
            int cc = c & 1023;
            int h = cc >> 6, d = cc & 63;
            float scl = (sel == 0) ? QSCALE : 1.0f;
            __half* dst = (sel == 0) ? g_q16 : (sel == 1) ? g_k16 : g_v16;
            float b0 = bias[c], b1 = bias[c + 1];
#pragma unroll
            for (int mt = 0; mt < 2; mt++) {
                int r0 = m0 + wm * 32 + mt * 16 + (lane >> 2);
#pragma unroll
                for (int half = 0; half < 2; half++) {
                    int r = r0 + half * 8;
                    float v0 = (acc[mt][nt][2 * half] + b0) * scl;
                    float v1 = (acc[mt][nt][2 * half + 1] + b1) * scl;
                    size_t o = ((size_t)h * LQ + r) * 64 + d;
                    *(__half2*)&dst[o] = __floats2half2_rn(v0, v1);
                }
            }
        }
    }
}

// ---------------------------------------------------------------------------
// Full-fp16 HMMA flash attention, causal, base-2 online softmax.
// 128 threads (4 warps x 16 q-rows = 64-row q-tile) per head.
// Single-pass QK^T and PV. K|V tiles per stage, 2-stage cp.async.
// ---------------------------------------------------------------------------
#define FT_ST 72
#define FT_TILE (64 * FT_ST * 2)   // 9216
#define FT_STAGE (2 * FT_TILE)     // 18432 (K, V)
#define FT_SMEM (2 * FT_STAGE)     // 36864

__global__ __launch_bounds__(128)
void flash_mma() {
    const int h = blockIdx.y;
    const int qt = (int)gridDim.x - 1 - (int)blockIdx.x; // heavy tiles first
    const int tid = threadIdx.x, lane = tid & 31, wid = tid >> 5;
    extern __shared__ __align__(16) char sm[];
    const uint32_t u0 = (uint32_t)__cvta_generic_to_shared(sm);
    const size_t hbase = (size_t)h * LQ * HDIM;

    // ---- Q fragments (fp16) straight from gmem ----
    const int qrow = qt * 64 + wid * 16 + (lane >> 2);
    uint32_t qh[4][4];
#pragma unroll
    for (int ks = 0; ks < 4; ks++) {
        int col = ks * 16 + ((lane & 3) << 1);
        size_t b00 = hbase + (size_t)qrow * 64 + col;
        qh[ks][0] = *(const uint32_t*)&g_q16[b00];
        qh[ks][1] = *(const uint32_t*)&g_q16[b00 + 8 * 64];
        qh[ks][2] = *(const uint32_t*)&g_q16[b00 + 8];
        qh[ks][3] = *(const uint32_t*)&g_q16[b00 + 8 * 64 + 8];
    }

    auto issue = [&](int kt) {
        const uint32_t sb = u0 + (kt & 1) * FT_STAGE;
#pragma unroll
        for (int r = 0; r < 8; r++) {
            const int t = r >> 2;                    // 0=K 1=V
            const int local = ((r & 3) << 7) + tid;  // 0..511
            const int row = local >> 3, c = local & 7;
            const __half* src = (t == 0) ? g_k16 : g_v16;
            CPA(sb + t * FT_TILE + row * (FT_ST * 2) + c * 16,
                src + hbase + (size_t)(kt * 64 + row) * 64 + c * 8);
        }
        CPC();
    };

    float o[8][4] = {};
    float m0 = -1e30f, m1 = -1e30f, l0 = 0.f, l1 = 0.f;
    const int grow0 = qrow;

    issue(0);
    for (int kt = 0; kt <= qt; ++kt) {
        CPW0();
        __syncthreads();
        if (kt < qt) issue(kt + 1);
        const uint32_t sb = u0 + (kt & 1) * FT_STAGE;
        const uint32_t uK = sb, uV = sb + FT_TILE;

        // ---- S = Q K^T (single fp16 pass) ----
        float s[8][4] = {};
#pragma unroll
        for (int ks = 0; ks < 4; ks++) {
#pragma unroll
            for (int np = 0; np < 4; np++) {
                uint32_t b4[4];
                int n = np * 16 + ((lane >> 4) << 3) + (lane & 7);
                int k = ks * 16 + (((lane >> 3) & 1) << 3);
                ldsm4(b4, uK + (n * FT_ST + k) * 2);
                mma16816h(s[2 * np], qh[ks], b4[0], b4[1]);
                mma16816h(s[2 * np + 1], qh[ks], b4[2], b4[3]);
            }
        }

        if (kt == qt) {  // causal mask on diagonal tile
#pragma unroll
            for (int nt = 0; nt < 8; nt++) {
                int c0 = kt * 64 + nt * 8 + ((lane & 3) << 1);
                if (c0 > grow0) s[nt][0] = -1e30f;
                if (c0 + 1 > grow0) s[nt][1] = -1e30f;
                if (c0 > grow0 + 8) s[nt][2] = -1e30f;
                if (c0 + 1 > grow0 + 8) s[nt][3] = -1e30f;
            }
        }

        // ---- online softmax (base-2) ----
        float mx0 = -1e30f, mx1 = -1e30f;
#pragma unroll
        for (int nt = 0; nt < 8; nt++) {
            mx0 = fmaxf(mx0, fmaxf(s[nt][0], s[nt][1]));
            mx1 = fmaxf(mx1, fmaxf(s[nt][2], s[nt][3]));
        }
        mx0 = fmaxf(mx0, __shfl_xor_sync(0xffffffffu, mx0, 1));
        mx0 = fmaxf(mx0, __shfl_xor_sync(0xffffffffu, mx0, 2));
        mx1 = fmaxf(mx1, __shfl_xor_sync(0xffffffffu, mx1, 1));
        mx1 = fmaxf(mx1, __shfl_xor_sync(0xffffffffu, mx1, 2));
        float mn0 = fmaxf(m0, mx0), mn1 = fmaxf(m1, mx1);
        float corr0 = ex2f(m0 - mn0), corr1 = ex2f(m1 - mn1);
        m0 = mn0; m1 = mn1;
        float ps0 = 0.f, ps1 = 0.f;
#pragma unroll
        for (int nt = 0; nt < 8; nt++) {
            s[nt][0] = ex2f(s[nt][0] - mn0);
            s[nt][1] = ex2f(s[nt][1] - mn0);
            s[nt][2] = ex2f(s[nt][2] - mn1);
            s[nt][3] = ex2f(s[nt][3] - mn1);
            ps0 += s[nt][0] + s[nt][1];
            ps1 += s[nt][2] + s[nt][3];
        }
        ps0 += __shfl_xor_sync(0xffffffffu, ps0, 1);
        ps0 += __shfl_xor_sync(0xffffffffu, ps0, 2);
        ps1 += __shfl_xor_sync(0xffffffffu, ps1, 1);
        ps1 += __shfl_xor_sync(0xffffffffu, ps1, 2);
        l0 = l0 * corr0 + ps0;
        l1 = l1 * corr1 + ps1;
#pragma unroll
        for (int nt = 0; nt < 8; nt++) {
            o[nt][0] *= corr0; o[nt][1] *= corr0;
            o[nt][2] *= corr1; o[nt][3] *= corr1;
        }

        // ---- O += P V (single fp16 pass) ----
#pragma unroll
        for (int ks = 0; ks < 4; ks++) {
            uint32_t a[4];
            a[0] = packh(s[2 * ks][0], s[2 * ks][1]);
            a[1] = packh(s[2 * ks][2], s[2 * ks][3]);
            a[2] = packh(s[2 * ks + 1][0], s[2 * ks + 1][1]);
            a[3] = packh(s[2 * ks + 1][2], s[2 * ks + 1][3]);
            int row = ks * 16 + ((lane >> 3) & 1) * 8 + (lane & 7);
#pragma unroll
            for (int np = 0; np < 4; np++) {
                uint32_t b4[4];
                int dc = np * 16 + ((lane >> 4) << 3);
                ldsm4t(b4, uV + (row * FT_ST + dc) * 2);
                mma16816h(o[2 * np], a, b4[0], b4[1]);
                mma16816h(o[2 * np + 1], a, b4[2], b4[3]);
            }
        }
    }

    // ---- epilogue: normalize, write fp16 [L][C] ----
    float inv0 = 1.f / l0, inv1 = 1.f / l1;
#pragma unroll
    for (int nt = 0; nt < 8; nt++) {
        int c = h * 64 + nt * 8 + ((lane & 3) << 1);
        *(__half2*)&g_a16[(size_t)grow0 * CDIM + c] =
            __floats2half2_rn(o[nt][0] * inv0, o[nt][1] * inv0);
        *(__half2*)&g_a16[(size_t)(grow0 + 8) * CDIM + c] =
            __floats2half2_rn(o[nt][2] * inv1, o[nt][3] * inv1);
    }
}

// ---------------------------------------------------------------------------
// Launch
// ---------------------------------------------------------------------------
extern "C" void kernel_launch(void* const* d_in, const int* in_sizes, int n_in,
                              void* d_out, int out_size) {
    (void)in_sizes; (void)n_in; (void)out_size;
    const float* x = (const float*)d_in[0];
    const float* Wqkv = (const float*)d_in[1];
    const float* bqkv = (const float*)d_in[2];
    const float* Wout = (const float*)d_in[3];
    const float* bout = (const float*)d_in[4];
    float* out = (float*)d_out;

    __half *x16, *a16, *wq, *wo;
    cudaGetSymbolAddress((void**)&x16, g_x16);
    cudaGetSymbolAddress((void**)&a16, g_a16);
    cudaGetSymbolAddress((void**)&wq, g_wq16);
    cudaGetSymbolAddress((void**)&wo, g_wo16);

    static int attr_set = 0;
    if (!attr_set) {
        cudaFuncSetAttribute(gemm3<0>, cudaFuncAttributeMaxDynamicSharedMemorySize, G_SMEM);
        cudaFuncSetAttribute(gemm3<1>, cudaFuncAttributeMaxDynamicSharedMemorySize, G_SMEM);
        cudaFuncSetAttribute(flash_mma, cudaFuncAttributeMaxDynamicSharedMemorySize, FT_SMEM);
        attr_set = 1;
    }

    // prep: X -> fp16, transpose-convert weights fp16
    cvt16_kernel<<<(LQ * CDIM) / 256, 256>>>(x, x16, LQ * CDIM);
    tcvt_kernel<<<dim3(C3 / 32, CDIM / 32), 256>>>(Wqkv, wq, CDIM, C3);
    tcvt_kernel<<<dim3(CDIM / 32, CDIM / 32), 256>>>(Wout, wo, CDIM, CDIM);

    // 1) QKV projection (fp16 single-pass) + fused per-head epilogue
    gemm3<1><<<dim3(C3 / 128, LQ / 128), 256, G_SMEM>>>(
        x16, wq, bqkv, nullptr, LQ, C3, CDIM);

    // 2) causal flash attention (full fp16)
    flash_mma<<<dim3(LQ / 64, NHEADS), 128, FT_SMEM>>>();

    // 3) output projection (fp16 single-pass)
    gemm3<0><<<dim3(CDIM / 128, LQ / 128), 256, G_SMEM>>>(
        a16, wo, bout, out, LQ, CDIM, CDIM);
}